// round 6
// baseline (speedup 1.0000x reference)
#include <cuda_runtime.h>
#include <cuda_fp16.h>

#define V_N  100000
#define B_N  8
#define FC_N 200000
#define U_N  1024
#define T_N  110000
#define K_N  2
#define EPS_F 1e-5f

#define VB   64                    // vertices per block (sample pass)
#define NTAP (VB * K_N * 4)        // 512 tap tasks per block

// Scratch:
__device__ float4 g_vt[V_N * B_N];   // transposed verts [v][b], 12.8 MB
__device__ float4 g_vn[V_N * B_N];   // accumulated vertex normals [v][b], 12.8 MB
__device__ uint2  g_vnh[V_N * B_N];  // normalized vn as half4 [v][b], 6.4 MB

__device__ __forceinline__ void red_add_v4(float4* ptr, float x, float y, float z) {
    asm volatile("red.global.add.v4.f32 [%0], {%1, %2, %3, %4};"
                 :: "l"(ptr), "f"(x), "f"(y), "f"(z), "f"(0.0f)
                 : "memory");
}

// Transpose verts -> g_vt[v*8+b] AND zero g_vn. b fastest => coalesced writes.
__global__ __launch_bounds__(256) void prep_kernel(const float* __restrict__ verts) {
    int i = blockIdx.x * blockDim.x + threadIdx.x;
    if (i >= V_N * B_N) return;
    int v = i >> 3;
    int b = i & 7;
    const float* p = verts + (size_t)b * (V_N * 3) + v * 3;
    float x = __ldg(p), y = __ldg(p + 1), z = __ldg(p + 2);
    g_vt[i] = make_float4(x, y, z, 0.f);
    g_vn[i] = make_float4(0.f, 0.f, 0.f, 0.f);
}

// One thread per (face, batch); b fastest. Coalesced 128B/8-lane vertex loads,
// 3 vector reductions per thread.
__global__ __launch_bounds__(256) void face_pass_kernel(const int* __restrict__ vi)
{
    int tid = blockIdx.x * blockDim.x + threadIdx.x;
    if (tid >= FC_N * B_N) return;
    int f = tid >> 3;
    int b = tid & 7;

    int i0 = __ldg(&vi[f * 3 + 0]);
    int i1 = __ldg(&vi[f * 3 + 1]);
    int i2 = __ldg(&vi[f * 3 + 2]);

    float4 A  = __ldg(&g_vt[i0 * B_N + b]);
    float4 Bv = __ldg(&g_vt[i1 * B_N + b]);
    float4 C  = __ldg(&g_vt[i2 * B_N + b]);

    float e1x = Bv.x - A.x, e1y = Bv.y - A.y, e1z = Bv.z - A.z;
    float e2x = C.x - A.x,  e2y = C.y - A.y,  e2z = C.z - A.z;
    float nx = e1y * e2z - e1z * e2y;
    float ny = e1z * e2x - e1x * e2z;
    float nz = e1x * e2y - e1y * e2x;

    float nrm = sqrtf(nx * nx + ny * ny + nz * nz);
    if (nrm >= EPS_F) {
        float inv = 1.f / nrm;
        nx *= inv; ny *= inv; nz *= inv;
    }

    red_add_v4(&g_vn[i0 * B_N + b], nx, ny, nz);
    red_add_v4(&g_vn[i1 * B_N + b], nx, ny, nz);
    red_add_v4(&g_vn[i2 * B_N + b], nx, ny, nz);
}

// Normalize in fp32, emit half4.
__global__ __launch_bounds__(256) void norm_vn_kernel() {
    int i = blockIdx.x * blockDim.x + threadIdx.x;
    if (i >= V_N * B_N) return;
    float4 v = g_vn[i];
    float nrm = sqrtf(v.x * v.x + v.y * v.y + v.z * v.z);
    if (nrm >= EPS_F) {
        float inv = 1.f / nrm;
        v.x *= inv; v.y *= inv; v.z *= inv;
    }
    __half2 xy = __floats2half2_rn(v.x, v.y);
    __half2 z0 = __floats2half2_rn(v.z, 0.f);
    uint2 u;
    *reinterpret_cast<__half2*>(&u.x) = xy;
    *reinterpret_cast<__half2*>(&u.y) = z0;
    g_vnh[i] = u;
}

// Two-stage sample pass. Block = 64 vertices.
// Stage 1: 512 tap-tasks (vloc,k,tap) over 256 threads x2: pixel math once per
//          tap -> smem as int4 (j0,j1,j2,valid) + float4 (w0,w1,w2,-).
// Stage 2: 256 threads = (vloc, bpair): per tap 2x LDS.128 + 3x LDG.128
//          (uint4 = 2 batches of half4), 4 lanes per vertex-group.
__global__ __launch_bounds__(256) void sample_pass_kernel(
    const float* __restrict__ bary,
    const float* __restrict__ vt,
    const int*   __restrict__ idximg,
    const int*   __restrict__ v2uv,
    float*       __restrict__ out)
{
    __shared__ int4   sj[NTAP];               // j0,j1,j2,valid
    __shared__ float4 sw[NTAP];               // w0,w1,w2,pad
    __shared__ float  sout[VB * B_N * 3];     // [b][vloc*3+c]

    int local = threadIdx.x;

    // ---- stage 1 ----
    #pragma unroll
    for (int it = 0; it < 2; it++) {
        int task = local + it * 256;
        int vloc = task >> 3;
        int k    = (task >> 2) & 1;
        int tap  = task & 3;
        int v    = blockIdx.x * VB + vloc;

        int4   J = make_int4(0, 0, 0, 0);
        float4 W = make_float4(0.f, 0.f, 0.f, 0.f);

        if (v < V_N) {
            int t = __ldg(&v2uv[v * K_N + k]);
            float u  = __ldg(&vt[t * 2 + 0]);
            float wv = __ldg(&vt[t * 2 + 1]);

            // ix = ((2u-1 + 1)*W - 1)*0.5 = u*W - 0.5
            float ix = u  * (float)U_N - 0.5f;
            float iy = wv * (float)U_N - 0.5f;
            float x0f = floorf(ix), y0f = floorf(iy);
            int x0 = (int)x0f, y0 = (int)y0f;
            float wx1 = ix - x0f, wx0 = 1.f - wx1;
            float wy1 = iy - y0f, wy0 = 1.f - wy1;

            int xi = x0 + (tap & 1);
            int yi = y0 + (tap >> 1);
            bool inb = (xi >= 0) & (xi < U_N) & (yi >= 0) & (yi < U_N);
            int xc = min(max(xi, 0), U_N - 1);
            int yc = min(max(yi, 0), U_N - 1);
            int pix = yc * U_N + xc;

            int a0 = __ldg(&idximg[pix * 3 + 0]);
            int a1 = __ldg(&idximg[pix * 3 + 1]);
            int a2 = __ldg(&idximg[pix * 3 + 2]);
            bool valid = inb & (a0 != -1) & (a1 != -1) & (a2 != -1);

            if (valid) {
                float wt = ((tap & 1) ? wx1 : wx0) * ((tap >> 1) ? wy1 : wy0);
                float b0 = __ldg(&bary[pix * 3 + 0]);
                float b1 = __ldg(&bary[pix * 3 + 1]);
                float b2 = __ldg(&bary[pix * 3 + 2]);
                J.x = min(max(a0, 0), V_N - 1);
                J.y = min(max(a1, 0), V_N - 1);
                J.z = min(max(a2, 0), V_N - 1);
                J.w = 1;
                W.x = wt * b0; W.y = wt * b1; W.z = wt * b2;
            }
        }
        sj[task] = J;
        sw[task] = W;
    }
    __syncthreads();

    // ---- stage 2: (vloc, bpair) ----
    {
        int vloc  = local >> 2;           // 0..63
        int bpair = local & 3;            // 0..3 -> batches 2*bp, 2*bp+1

        // accumulators for the two batches
        float ex = 0.f, ey = 0.f, ez = 0.f;   // b even
        float ox = 0.f, oy = 0.f, oz = 0.f;   // b odd

        const uint4* vnh4 = reinterpret_cast<const uint4*>(g_vnh);

        #pragma unroll
        for (int e = 0; e < 8; e++) {
            int idx = vloc * 8 + e;
            int4 J = sj[idx];
            if (J.w == 0) continue;       // uniform across 4-lane group
            float4 W = sw[idx];

            // uint4 = [half2(x,y), half2(z,0)] for b_even then b_odd
            uint4 h0 = __ldg(&vnh4[J.x * 4 + bpair]);
            uint4 h1 = __ldg(&vnh4[J.y * 4 + bpair]);
            uint4 h2 = __ldg(&vnh4[J.z * 4 + bpair]);

            float2 a0 = __half22float2(*reinterpret_cast<__half2*>(&h0.x));
            float  a0z = __low2float(*reinterpret_cast<__half2*>(&h0.y));
            float2 b0 = __half22float2(*reinterpret_cast<__half2*>(&h0.z));
            float  b0z = __low2float(*reinterpret_cast<__half2*>(&h0.w));

            float2 a1 = __half22float2(*reinterpret_cast<__half2*>(&h1.x));
            float  a1z = __low2float(*reinterpret_cast<__half2*>(&h1.y));
            float2 b1 = __half22float2(*reinterpret_cast<__half2*>(&h1.z));
            float  b1z = __low2float(*reinterpret_cast<__half2*>(&h1.w));

            float2 a2 = __half22float2(*reinterpret_cast<__half2*>(&h2.x));
            float  a2z = __low2float(*reinterpret_cast<__half2*>(&h2.y));
            float2 b2 = __half22float2(*reinterpret_cast<__half2*>(&h2.z));
            float  b2z = __low2float(*reinterpret_cast<__half2*>(&h2.w));

            ex += W.x * a0.x + W.y * a1.x + W.z * a2.x;
            ey += W.x * a0.y + W.y * a1.y + W.z * a2.y;
            ez += W.x * a0z  + W.y * a1z  + W.z * a2z;

            ox += W.x * b0.x + W.y * b1.x + W.z * b2.x;
            oy += W.x * b0.y + W.y * b1.y + W.z * b2.y;
            oz += W.x * b0z  + W.y * b1z  + W.z * b2z;
        }

        float sc = 1.f / (float)K_N;
        int be = bpair * 2, bo = bpair * 2 + 1;
        sout[be * (VB * 3) + vloc * 3 + 0] = ex * sc;
        sout[be * (VB * 3) + vloc * 3 + 1] = ey * sc;
        sout[be * (VB * 3) + vloc * 3 + 2] = ez * sc;
        sout[bo * (VB * 3) + vloc * 3 + 0] = ox * sc;
        sout[bo * (VB * 3) + vloc * 3 + 1] = oy * sc;
        sout[bo * (VB * 3) + vloc * 3 + 2] = oz * sc;
    }
    __syncthreads();

    // Coalesced write-out: out[b][v][c], VB*3 floats per batch per block.
    int v0 = blockIdx.x * VB;
    for (int i = local; i < VB * B_N * 3; i += 256) {
        int bb = i / (VB * 3);
        int r  = i - bb * (VB * 3);       // vloc*3 + c
        int vv = v0 + r / 3;
        if (vv < V_N) out[(size_t)bb * (V_N * 3) + (size_t)v0 * 3 + r] = sout[i];
    }
}

extern "C" void kernel_launch(void* const* d_in, const int* in_sizes, int n_in,
                              void* d_out, int out_size)
{
    const float* verts  = (const float*)d_in[0];  // [B, V, 3]
    const float* bary   = (const float*)d_in[1];  // [U, U, 3]
    const float* vt     = (const float*)d_in[2];  // [T, 2]
    const int*   vi     = (const int*)  d_in[3];  // [Fc, 3]
    const int*   idximg = (const int*)  d_in[4];  // [U, U, 3]
    const int*   v2uv   = (const int*)  d_in[5];  // [V, K]
    float*       out    = (float*)d_out;          // [B, V, 3]

    (void)in_sizes; (void)n_in; (void)out_size;

    prep_kernel<<<(V_N * B_N + 255) / 256, 256>>>(verts);
    face_pass_kernel<<<(FC_N * B_N + 255) / 256, 256>>>(vi);
    norm_vn_kernel<<<(V_N * B_N + 255) / 256, 256>>>();
    sample_pass_kernel<<<(V_N + VB - 1) / VB, 256>>>(bary, vt, idximg, v2uv, out);
}